// round 12
// baseline (speedup 1.0000x reference)
#include <cuda_runtime.h>
#include <cuda_fp16.h>
#include <cstdint>

// out[b,n,f] = sum_m A[b,n,m] * X[b,m,f] + bias[f]
// A: [8,4096,4096] fp32, X: [8,4096,64] fp32, bias [64].
//
// Single-launch fused kernel (R11) with two refinements:
//  - PER-BATCH software barrier: CTA (b,ct) only needs Xt[b], written by the
//    37 CTAs of batch b -> quorum 37 instead of 296 (less skew, L2 locality).
//  - A sub0 fully staged (LDG+STS) and A sub1 prefetched BEFORE the spin
//    (A never depends on g_Xt); post-barrier exposure = two B L2 latencies.
// GEMM main loop is R9 verbatim (fp16 mma.sync, 2x KC=64 sub-chunks per
// iteration, register-staged double buffer, 16-row balanced split, 296 CTAs).

#define NBATCH  8
#define NN      4096
#define FF      64
#define CTAS_B  37
#define GRID    (NBATCH * CTAS_B)   // 296
#define MAXG    7
#define NSUB    64                  // KC=64 sub-chunks
#define NIT     32                  // 2 sub-chunks per iteration

#define SUB_A   14336               // 112 rows x 128B fp16
#define SUB_B   8192                // 64 f-rows x 128B fp16
#define STB2    (2 * (SUB_A + SUB_B))   // 45056 per stage
#define OFF_B   (2 * SUB_A)             // 28672 within stage
#define SMEM_DYN (2 * STB2)             // 90112

__device__ __half g_Xt[NBATCH * FF * NN];   // [b][f][k] fp16
__device__ unsigned g_bar[NBATCH];          // per-batch monotonic epoch counters

__device__ __forceinline__ uint32_t smem_u32(const void* p) {
    uint32_t a;
    asm("{ .reg .u64 t; cvta.to.shared.u64 t, %1; cvt.u32.u64 %0, t; }"
        : "=r"(a) : "l"(p));
    return a;
}
#define SW(o) ((o) ^ (((o) >> 3) & 0x70))

__global__ __launch_bounds__(256, 2) void gemm_f16_fused2(
    const float* __restrict__ A,
    const float* __restrict__ X,
    const float* __restrict__ bias,
    float* __restrict__ out)
{
    extern __shared__ char ds[];
    const uint32_t sb = smem_u32(ds);

    const int tid  = threadIdx.x;
    const int wid  = tid >> 5;
    const int lane = tid & 31;

    const int b  = blockIdx.x / CTAS_B;
    const int ct = blockIdx.x % CTAS_B;

    // ============ phase 1: convert my batch's slab share into g_Xt =========
    // batch b has 128 slabs of 32k x 64f; CTA ct converts [ct*128/37, ...).
    {
        float* tt = reinterpret_cast<float*>(ds);     // [32][65]
        const int tx = tid & 31;
        const int ty = tid >> 5;
        const int s0 = (ct * 128) / CTAS_B;
        const int s1 = ((ct + 1) * 128) / CTAS_B;
        for (int s = s0; s < s1; ++s) {
            const int k0 = s * 32;
#pragma unroll
            for (int i = 0; i < 4; ++i) {
                const int r = ty + 8 * i;
                const float* src = X + ((size_t)b * NN + k0 + r) * FF;
                tt[r * 65 + tx]      = src[tx];
                tt[r * 65 + tx + 32] = src[tx + 32];
            }
            __syncthreads();
#pragma unroll
            for (int j = 0; j < 8; ++j) {
                const int f = ty + 8 * j;
                g_Xt[((size_t)b * FF + f) * NN + k0 + tx] =
                    __float2half_rn(tt[tx * 65 + f]);
            }
            __syncthreads();
        }
    }

    // ---- arrive at per-batch barrier (release) ----
    __threadfence();
    __syncthreads();
    unsigned bar_target = 0;
    if (tid == 0) {
        const unsigned my = atomicAdd(&g_bar[b], 1u);
        bar_target = my - (my % (unsigned)CTAS_B) + (unsigned)CTAS_B;
    }

    // ============ phase 2: GEMM (R9 core) ==================================
    const int g0 = (ct * 256) / CTAS_B;
    const int g1 = ((ct + 1) * 256) / CTAS_B;
    const int NG = g1 - g0;             // 6 or 7 (16-row groups)
    const int nrows = NG * 16;

    const float*  Ab = A + ((size_t)b * NN + (size_t)g0 * 16) * NN;
    const __half* Xb = g_Xt + (size_t)b * FF * NN;

    const int arow = tid >> 4;
    const int ac4  = tid & 15;
    const int brow = tid >> 3;
    const int bc   = tid & 7;
    const float*  a_ld = Ab + (size_t)arow * NN + ac4 * 4;
    const __half* b_ld = Xb + (size_t)brow * NN + bc * 8;
    const uint32_t a_sts = SW((uint32_t)(arow * 128 + ac4 * 8));
    const uint32_t b_sts = SW((uint32_t)(brow * 128 + bc * 16));

    const int li = lane >> 3;
    const int lr = lane & 7;
    const uint32_t a_off =
        (uint32_t)((wid * 16 + (li & 1) * 8 + lr) * 128 + (li >> 1) * 16);
    const uint32_t b_off =
        (uint32_t)(((li >> 1) * 8 + lr) * 128 + (li & 1) * 16);

    float acc[8][4];
#pragma unroll
    for (int n = 0; n < 8; ++n)
#pragma unroll
        for (int j = 0; j < 4; ++j) acc[n][j] = 0.0f;

    float4 pa[MAXG];
    uint4  pb[2];

    auto ldg_a = [&](int s) {
        const size_t ko = (size_t)s * 64;
#pragma unroll
        for (int i = 0; i < MAXG; ++i)
            if (16 * i < nrows)
                pa[i] = *reinterpret_cast<const float4*>(
                    a_ld + (size_t)(16 * i) * NN + ko);
    };
    auto ldg_b = [&](int s) {
        const size_t ko = (size_t)s * 64;
#pragma unroll
        for (int i = 0; i < 2; ++i)
            pb[i] = *reinterpret_cast<const uint4*>(
                b_ld + (size_t)(32 * i) * NN + ko);
    };
    auto sts_a = [&](uint32_t abase) {
#pragma unroll
        for (int i = 0; i < MAXG; ++i)
            if (16 * i < nrows) {
                __half2 h0 = __floats2half2_rn(pa[i].x, pa[i].y);
                __half2 h1 = __floats2half2_rn(pa[i].z, pa[i].w);
                asm volatile("st.shared.v2.b32 [%0], {%1, %2};"
                             :: "r"(abase + a_sts + (uint32_t)i * 2048),
                                "r"(*(uint32_t*)&h0), "r"(*(uint32_t*)&h1)
                             : "memory");
            }
    };
    auto sts_b = [&](uint32_t bbase) {
#pragma unroll
        for (int i = 0; i < 2; ++i)
            asm volatile("st.shared.v4.b32 [%0], {%1,%2,%3,%4};"
                         :: "r"(bbase + b_sts + (uint32_t)i * 4096),
                            "r"(pb[i].x), "r"(pb[i].y), "r"(pb[i].z), "r"(pb[i].w)
                         : "memory");
    };
    auto compute_sub = [&](uint32_t abase, uint32_t bbase) {
#pragma unroll
        for (int ks = 0; ks < 4; ++ks) {
            uint32_t a0, a1, a2, a3;
            asm volatile(
                "ldmatrix.sync.aligned.m8n8.x4.shared.b16 {%0,%1,%2,%3}, [%4];"
                : "=r"(a0), "=r"(a1), "=r"(a2), "=r"(a3)
                : "r"(abase + SW(a_off + (uint32_t)ks * 32)));
#pragma unroll
            for (int p = 0; p < 4; ++p) {
                uint32_t b0, b1, b2, b3;
                asm volatile(
                    "ldmatrix.sync.aligned.m8n8.x4.shared.b16 {%0,%1,%2,%3}, [%4];"
                    : "=r"(b0), "=r"(b1), "=r"(b2), "=r"(b3)
                    : "r"(bbase + SW(b_off + (uint32_t)p * 2048 + (uint32_t)ks * 32)));
                asm volatile(
                    "mma.sync.aligned.m16n8k16.row.col.f32.f16.f16.f32 "
                    "{%0,%1,%2,%3}, {%4,%5,%6,%7}, {%8,%9}, {%0,%1,%2,%3};"
                    : "+f"(acc[2*p][0]), "+f"(acc[2*p][1]),
                      "+f"(acc[2*p][2]), "+f"(acc[2*p][3])
                    : "r"(a0), "r"(a1), "r"(a2), "r"(a3), "r"(b0), "r"(b1));
                asm volatile(
                    "mma.sync.aligned.m16n8k16.row.col.f32.f16.f16.f32 "
                    "{%0,%1,%2,%3}, {%4,%5,%6,%7}, {%8,%9}, {%0,%1,%2,%3};"
                    : "+f"(acc[2*p+1][0]), "+f"(acc[2*p+1][1]),
                      "+f"(acc[2*p+1][2]), "+f"(acc[2*p+1][3])
                    : "r"(a0), "r"(a1), "r"(a2), "r"(a3), "r"(b2), "r"(b3));
            }
        }
    };

    // ---- A-only staging while the barrier settles (A never needs g_Xt) ----
    ldg_a(0);
    sts_a(sb);               // A sub0 -> buffer0 (overwrites tt; local order ok)
    ldg_a(1);                // A sub1 -> regs, in flight during the spin

    // ---- wait at per-batch barrier (acquire) ----
    if (tid == 0) {
        unsigned v;
        do {
            asm volatile("ld.acquire.gpu.global.u32 %0, [%1];"
                         : "=r"(v) : "l"(&g_bar[b]));
            if (v >= bar_target) break;
            __nanosleep(32);
        } while (true);
    }
    __syncthreads();

    // ---- post-barrier: B-only prologue (two L2 latencies exposed) ----
    ldg_b(0);
    sts_b(sb + OFF_B);
    sts_a(sb + SUB_A);       // A sub1 from regs
    ldg_b(1);
    sts_b(sb + OFF_B + SUB_B);
    ldg_a(2); ldg_b(2);
    __syncthreads();

    for (int C = 0; C < NIT; ++C) {
        const uint32_t cur = sb + (uint32_t)(C & 1) * STB2;
        const uint32_t nxt = sb + (uint32_t)((C + 1) & 1) * STB2;

        if (2 * C + 2 < NSUB) { sts_a(nxt); sts_b(nxt + OFF_B); }
        if (2 * C + 3 < NSUB) { ldg_a(2 * C + 3); ldg_b(2 * C + 3); }

        if (wid < NG) compute_sub(cur, cur + OFF_B);                 // sub 2C

        if (2 * C + 3 < NSUB) { sts_a(nxt + SUB_A); sts_b(nxt + OFF_B + SUB_B); }
        if (2 * C + 4 < NSUB) { ldg_a(2 * C + 4); ldg_b(2 * C + 4); }

        if (wid < NG) compute_sub(cur + SUB_A, cur + OFF_B + SUB_B); // sub 2C+1

        __syncthreads();
    }

    // ---- epilogue: add bias, store ----
    if (wid < NG) {
        const int g = lane >> 2, q = lane & 3;
        const int mlo = (g0 + wid) * 16 + g;
        float* o0 = out + ((size_t)b * NN + mlo) * FF;
        float* o1 = o0 + (size_t)8 * FF;
#pragma unroll
        for (int nt = 0; nt < 8; ++nt) {
            const int col = nt * 8 + q * 2;
            const float2 bv = *reinterpret_cast<const float2*>(bias + col);
            float2 v0 = make_float2(acc[nt][0] + bv.x, acc[nt][1] + bv.y);
            float2 v1 = make_float2(acc[nt][2] + bv.x, acc[nt][3] + bv.y);
            *reinterpret_cast<float2*>(o0 + col) = v0;
            *reinterpret_cast<float2*>(o1 + col) = v1;
        }
    }
}

extern "C" void kernel_launch(void* const* d_in, const int* in_sizes, int n_in,
                              void* d_out, int out_size)
{
    const float* A    = (const float*)d_in[0]; // adjacent [8,4096,4096]
    const float* X    = (const float*)d_in[1]; // annotations [8,4096,64]
    const float* bias = (const float*)d_in[2]; // bias [1,1,64]
    float* out = (float*)d_out;

    cudaFuncSetAttribute(gemm_f16_fused2,
                         cudaFuncAttributeMaxDynamicSharedMemorySize, SMEM_DYN);

    gemm_f16_fused2<<<GRID, 256, SMEM_DYN>>>(A, X, bias, out);
}

// round 13
// speedup vs baseline: 1.3689x; 1.3689x over previous
#include <cuda_runtime.h>
#include <cuda_fp16.h>
#include <cstdint>

// out[b,n,f] = sum_m A[b,n,m] * X[b,m,f] + bias[f]
// A: [8,4096,4096] fp32, X: [8,4096,64] fp32, bias [64].
//
// R11 (single launch, GLOBAL software barrier, R9 GEMM core) with ONE change:
// pre-barrier A staging. A never depends on g_Xt, so before the spin we
// LDG+STS the full A sub0 into buffer0 and prefetch A sub1 into registers;
// the post-barrier prologue is B-only (two L2 round-trips exposed). All other
// code (convert phase, global barrier, main loop, epilogue) is R11 verbatim.

#define NBATCH  8
#define NN      4096
#define FF      64
#define CTAS_B  37
#define GRID    (NBATCH * CTAS_B)   // 296
#define MAXG    7
#define NSUB    64                  // KC=64 sub-chunks
#define NIT     32                  // 2 sub-chunks per iteration

#define SUB_A   14336               // 112 rows x 128B fp16
#define SUB_B   8192                // 64 f-rows x 128B fp16
#define STB2    (2 * (SUB_A + SUB_B))   // 45056 per stage
#define OFF_B   (2 * SUB_A)             // 28672 within stage
#define SMEM_DYN (2 * STB2)             // 90112

__device__ __half g_Xt[NBATCH * FF * NN];   // [b][f][k] fp16
__device__ unsigned g_bar = 0;              // monotonic epoch barrier counter

__device__ __forceinline__ uint32_t smem_u32(const void* p) {
    uint32_t a;
    asm("{ .reg .u64 t; cvta.to.shared.u64 t, %1; cvt.u32.u64 %0, t; }"
        : "=r"(a) : "l"(p));
    return a;
}
#define SW(o) ((o) ^ (((o) >> 3) & 0x70))

__global__ __launch_bounds__(256, 2) void gemm_f16_fused3(
    const float* __restrict__ A,
    const float* __restrict__ X,
    const float* __restrict__ bias,
    float* __restrict__ out)
{
    extern __shared__ char ds[];
    const uint32_t sb = smem_u32(ds);

    const int tid  = threadIdx.x;
    const int wid  = tid >> 5;
    const int lane = tid & 31;

    // ================= phase 1: convert X -> g_Xt (my slab share) ==========
    {
        float* tt = reinterpret_cast<float*>(ds);     // [32][65]
        const int tx = tid & 31;
        const int ty = tid >> 5;
        const int s0 = (blockIdx.x * 1024) / GRID;
        const int s1 = ((blockIdx.x + 1) * 1024) / GRID;
        for (int s = s0; s < s1; ++s) {
            const int cb = s >> 7;
            const int k0 = (s & 127) * 32;
#pragma unroll
            for (int i = 0; i < 4; ++i) {
                const int r = ty + 8 * i;
                const float* src = X + ((size_t)cb * NN + k0 + r) * FF;
                tt[r * 65 + tx]      = src[tx];
                tt[r * 65 + tx + 32] = src[tx + 32];
            }
            __syncthreads();
#pragma unroll
            for (int j = 0; j < 8; ++j) {
                const int f = ty + 8 * j;
                g_Xt[((size_t)cb * FF + f) * NN + k0 + tx] =
                    __float2half_rn(tt[tx * 65 + f]);
            }
            __syncthreads();
        }
    }

    // ---- arrive at global barrier (release) ----
    __threadfence();
    __syncthreads();
    unsigned bar_target = 0;
    if (tid == 0) {
        const unsigned my = atomicAdd(&g_bar, 1u);
        bar_target = my - (my % (unsigned)GRID) + (unsigned)GRID;
    }

    // ================= phase 2: GEMM (R9 core) =============================
    const int b  = blockIdx.x / CTAS_B;
    const int ct = blockIdx.x % CTAS_B;
    const int g0 = (ct * 256) / CTAS_B;
    const int g1 = ((ct + 1) * 256) / CTAS_B;
    const int NG = g1 - g0;             // 6 or 7 (16-row groups)
    const int nrows = NG * 16;

    const float*  Ab = A + ((size_t)b * NN + (size_t)g0 * 16) * NN;
    const __half* Xb = g_Xt + (size_t)b * FF * NN;

    const int arow = tid >> 4;
    const int ac4  = tid & 15;
    const int brow = tid >> 3;
    const int bc   = tid & 7;
    const float*  a_ld = Ab + (size_t)arow * NN + ac4 * 4;
    const __half* b_ld = Xb + (size_t)brow * NN + bc * 8;
    const uint32_t a_sts = SW((uint32_t)(arow * 128 + ac4 * 8));
    const uint32_t b_sts = SW((uint32_t)(brow * 128 + bc * 16));

    const int li = lane >> 3;
    const int lr = lane & 7;
    const uint32_t a_off =
        (uint32_t)((wid * 16 + (li & 1) * 8 + lr) * 128 + (li >> 1) * 16);
    const uint32_t b_off =
        (uint32_t)(((li >> 1) * 8 + lr) * 128 + (li & 1) * 16);

    float acc[8][4];
#pragma unroll
    for (int n = 0; n < 8; ++n)
#pragma unroll
        for (int j = 0; j < 4; ++j) acc[n][j] = 0.0f;

    float4 pa[MAXG];
    uint4  pb[2];

    auto ldg_a = [&](int s) {
        const size_t ko = (size_t)s * 64;
#pragma unroll
        for (int i = 0; i < MAXG; ++i)
            if (16 * i < nrows)
                pa[i] = *reinterpret_cast<const float4*>(
                    a_ld + (size_t)(16 * i) * NN + ko);
    };
    auto ldg_b = [&](int s) {
        const size_t ko = (size_t)s * 64;
#pragma unroll
        for (int i = 0; i < 2; ++i)
            pb[i] = *reinterpret_cast<const uint4*>(
                b_ld + (size_t)(32 * i) * NN + ko);
    };
    auto sts_a = [&](uint32_t abase) {
#pragma unroll
        for (int i = 0; i < MAXG; ++i)
            if (16 * i < nrows) {
                __half2 h0 = __floats2half2_rn(pa[i].x, pa[i].y);
                __half2 h1 = __floats2half2_rn(pa[i].z, pa[i].w);
                asm volatile("st.shared.v2.b32 [%0], {%1, %2};"
                             :: "r"(abase + a_sts + (uint32_t)i * 2048),
                                "r"(*(uint32_t*)&h0), "r"(*(uint32_t*)&h1)
                             : "memory");
            }
    };
    auto sts_b = [&](uint32_t bbase) {
#pragma unroll
        for (int i = 0; i < 2; ++i)
            asm volatile("st.shared.v4.b32 [%0], {%1,%2,%3,%4};"
                         :: "r"(bbase + b_sts + (uint32_t)i * 4096),
                            "r"(pb[i].x), "r"(pb[i].y), "r"(pb[i].z), "r"(pb[i].w)
                         : "memory");
    };
    auto compute_sub = [&](uint32_t abase, uint32_t bbase) {
#pragma unroll
        for (int ks = 0; ks < 4; ++ks) {
            uint32_t a0, a1, a2, a3;
            asm volatile(
                "ldmatrix.sync.aligned.m8n8.x4.shared.b16 {%0,%1,%2,%3}, [%4];"
                : "=r"(a0), "=r"(a1), "=r"(a2), "=r"(a3)
                : "r"(abase + SW(a_off + (uint32_t)ks * 32)));
#pragma unroll
            for (int p = 0; p < 4; ++p) {
                uint32_t b0, b1, b2, b3;
                asm volatile(
                    "ldmatrix.sync.aligned.m8n8.x4.shared.b16 {%0,%1,%2,%3}, [%4];"
                    : "=r"(b0), "=r"(b1), "=r"(b2), "=r"(b3)
                    : "r"(bbase + SW(b_off + (uint32_t)p * 2048 + (uint32_t)ks * 32)));
                asm volatile(
                    "mma.sync.aligned.m16n8k16.row.col.f32.f16.f16.f32 "
                    "{%0,%1,%2,%3}, {%4,%5,%6,%7}, {%8,%9}, {%0,%1,%2,%3};"
                    : "+f"(acc[2*p][0]), "+f"(acc[2*p][1]),
                      "+f"(acc[2*p][2]), "+f"(acc[2*p][3])
                    : "r"(a0), "r"(a1), "r"(a2), "r"(a3), "r"(b0), "r"(b1));
                asm volatile(
                    "mma.sync.aligned.m16n8k16.row.col.f32.f16.f16.f32 "
                    "{%0,%1,%2,%3}, {%4,%5,%6,%7}, {%8,%9}, {%0,%1,%2,%3};"
                    : "+f"(acc[2*p+1][0]), "+f"(acc[2*p+1][1]),
                      "+f"(acc[2*p+1][2]), "+f"(acc[2*p+1][3])
                    : "r"(a0), "r"(a1), "r"(a2), "r"(a3), "r"(b2), "r"(b3));
            }
        }
    };

    // ---- pre-barrier A staging (A never needs g_Xt) ----
    ldg_a(0);
    sts_a(sb);      // A sub0 -> buffer0 (convert scratch reuse is CTA-local)
    ldg_a(1);       // A sub1 in flight during the spin

    // ---- wait at global barrier (acquire) ----
    if (tid == 0) {
        unsigned v;
        do {
            asm volatile("ld.acquire.gpu.global.u32 %0, [%1];"
                         : "=r"(v) : "l"(&g_bar));
            if (v >= bar_target) break;
            __nanosleep(32);
        } while (true);
    }
    __syncthreads();

    // ---- post-barrier: B-only prologue ----
    ldg_b(0);
    sts_b(sb + OFF_B);
    sts_a(sb + SUB_A);       // A sub1 from regs
    ldg_b(1);
    sts_b(sb + OFF_B + SUB_B);
    ldg_a(2); ldg_b(2);
    __syncthreads();

    for (int C = 0; C < NIT; ++C) {
        const uint32_t cur = sb + (uint32_t)(C & 1) * STB2;
        const uint32_t nxt = sb + (uint32_t)((C + 1) & 1) * STB2;

        if (2 * C + 2 < NSUB) { sts_a(nxt); sts_b(nxt + OFF_B); }
        if (2 * C + 3 < NSUB) { ldg_a(2 * C + 3); ldg_b(2 * C + 3); }

        if (wid < NG) compute_sub(cur, cur + OFF_B);                 // sub 2C

        if (2 * C + 3 < NSUB) { sts_a(nxt + SUB_A); sts_b(nxt + OFF_B + SUB_B); }
        if (2 * C + 4 < NSUB) { ldg_a(2 * C + 4); ldg_b(2 * C + 4); }

        if (wid < NG) compute_sub(cur + SUB_A, cur + OFF_B + SUB_B); // sub 2C+1

        __syncthreads();
    }

    // ---- epilogue: add bias, store ----
    if (wid < NG) {
        const int g = lane >> 2, q = lane & 3;
        const int mlo = (g0 + wid) * 16 + g;
        float* o0 = out + ((size_t)b * NN + mlo) * FF;
        float* o1 = o0 + (size_t)8 * FF;
#pragma unroll
        for (int nt = 0; nt < 8; ++nt) {
            const int col = nt * 8 + q * 2;
            const float2 bv = *reinterpret_cast<const float2*>(bias + col);
            float2 v0 = make_float2(acc[nt][0] + bv.x, acc[nt][1] + bv.y);
            float2 v1 = make_float2(acc[nt][2] + bv.x, acc[nt][3] + bv.y);
            *reinterpret_cast<float2*>(o0 + col) = v0;
            *reinterpret_cast<float2*>(o1 + col) = v1;
        }
    }
}

extern "C" void kernel_launch(void* const* d_in, const int* in_sizes, int n_in,
                              void* d_out, int out_size)
{
    const float* A    = (const float*)d_in[0]; // adjacent [8,4096,4096]
    const float* X    = (const float*)d_in[1]; // annotations [8,4096,64]
    const float* bias = (const float*)d_in[2]; // bias [1,1,64]
    float* out = (float*)d_out;

    cudaFuncSetAttribute(gemm_f16_fused3,
                         cudaFuncAttributeMaxDynamicSharedMemorySize, SMEM_DYN);

    gemm_f16_fused3<<<GRID, 256, SMEM_DYN>>>(A, X, bias, out);
}